// round 1
// baseline (speedup 1.0000x reference)
#include <cuda_runtime.h>

#define N_NODES  10000
#define N_EDGES  320000
#define N_GRAPHS 16
#define D_IN     256
#define D_H      64

// ---------------- device scratch (no allocations allowed) ----------------
__device__ float g_S[N_NODES * D_H];     // self projection (+bias)
__device__ float g_X[N_NODES * D_H];     // neighbor projection
__device__ float g_agg[N_NODES * D_H];   // edge-aggregated sums
__device__ float g_h1[N_NODES * D_H];    // layer1 output
__device__ float g_h2[N_NODES * D_H];    // layer2 output
__device__ float g_deg[N_NODES];         // in-degree (float)
__device__ float g_gsum[N_GRAPHS * D_H]; // readout partial sums
__device__ float g_gcnt[N_GRAPHS];       // nodes per graph

// ---------------- kernels ----------------

__global__ void zero_f(float* __restrict__ p, int n) {
    int t = blockIdx.x * blockDim.x + threadIdx.x;
    if (t < n) p[t] = 0.f;
}

// deg over edges (dst), graph counts over nodes, in one kernel
__global__ void deg_gcnt_kernel(const int* __restrict__ dst,
                                const int* __restrict__ gid) {
    int t = blockIdx.x * blockDim.x + threadIdx.x;
    if (t < N_EDGES) {
        atomicAdd(&g_deg[dst[t]], 1.0f);
    } else if (t < N_EDGES + N_NODES) {
        int i = t - N_EDGES;
        atomicAdd(&g_gcnt[gid[i]], 1.0f);
    }
}

// S = A @ Wself + b ; X = A @ Wneigh   (A: [N_NODES, K], W: [K, 64])
template <int K>
__global__ void project_kernel(const float* __restrict__ A,
                               const float* __restrict__ Wself,
                               const float* __restrict__ Wneigh,
                               const float* __restrict__ b) {
    __shared__ float sA[4][K];
    int c   = threadIdx.x;          // output column 0..63
    int r   = threadIdx.y;          // 0..3
    int row = blockIdx.x * 4 + r;

    // cooperative load of 4 A rows
    for (int k = threadIdx.x; k < K; k += 64)
        sA[r][k] = (row < N_NODES) ? A[row * K + k] : 0.f;
    __syncthreads();
    if (row >= N_NODES) return;

    float s = 0.f, x = 0.f;
#pragma unroll 8
    for (int k = 0; k < K; k++) {
        float a = sA[r][k];
        s = fmaf(a, __ldg(&Wself[k * D_H + c]), s);
        x = fmaf(a, __ldg(&Wneigh[k * D_H + c]), x);
    }
    g_S[row * D_H + c] = s + __ldg(&b[c]);
    g_X[row * D_H + c] = x;
}

// agg[dst] += X[src], vectorized 16B reductions; 16 threads per edge
__global__ void scatter_kernel(const int* __restrict__ src,
                               const int* __restrict__ dst) {
    unsigned t = blockIdx.x * blockDim.x + threadIdx.x;
    if (t >= (unsigned)N_EDGES * 16u) return;
    int e = (int)(t >> 4);
    int q = (int)(t & 15u);
    int s = src[e];
    int d = dst[e];
    float4 v = *reinterpret_cast<const float4*>(g_X + s * D_H + q * 4);
    float* addr = g_agg + d * D_H + q * 4;
    asm volatile("red.global.add.v4.f32 [%0], {%1, %2, %3, %4};"
                 :: "l"(addr), "f"(v.x), "f"(v.y), "f"(v.z), "f"(v.w)
                 : "memory");
}

// out = act(S + agg/max(deg,1))
template <bool RELU>
__global__ void finalize_kernel(float* __restrict__ out) {
    int t = blockIdx.x * blockDim.x + threadIdx.x;
    if (t >= N_NODES * D_H) return;
    int i = t >> 6;  // / D_H
    float v = g_S[t] + g_agg[t] / fmaxf(g_deg[i], 1.0f);
    out[t] = RELU ? fmaxf(v, 0.f) : v;
}

// per-graph partial sums of h3 into g_gsum (block-local smem accumulation)
__global__ void readout_kernel(const float* __restrict__ h,
                               const int* __restrict__ gid) {
    __shared__ float acc[N_GRAPHS][D_H];
    int c = threadIdx.x;  // 0..63
#pragma unroll
    for (int g = 0; g < N_GRAPHS; g++) acc[g][c] = 0.f;
    __syncthreads();

    const int ROWS = 250;
    int row0 = blockIdx.x * ROWS;
    int row1 = row0 + ROWS < N_NODES ? row0 + ROWS : N_NODES;
    for (int row = row0; row < row1; row++)
        acc[gid[row]][c] += h[row * D_H + c];

    __syncthreads();
#pragma unroll
    for (int g = 0; g < N_GRAPHS; g++)
        atomicAdd(&g_gsum[g * D_H + c], acc[g][c]);
}

// out_feat = gsum/max(cnt,1); out = out_feat @ Wcls + bcls
__global__ void head_kernel(const float* __restrict__ Wcls,
                            const float* __restrict__ bcls,
                            float* __restrict__ out,
                            float* __restrict__ out_feat) {
    __shared__ float sf[N_GRAPHS * D_H];
    int t = threadIdx.x;
    for (int idx = t; idx < N_GRAPHS * D_H; idx += blockDim.x) {
        int g = idx >> 6;
        float m = g_gsum[idx] / fmaxf(g_gcnt[g], 1.0f);
        sf[idx] = m;
        out_feat[idx] = m;
    }
    __syncthreads();
    if (t < N_GRAPHS * 2) {
        int g = t >> 1, j = t & 1;
        float s = bcls[j];
#pragma unroll
        for (int c = 0; c < D_H; c++)
            s = fmaf(sf[g * D_H + c], Wcls[c * 2 + j], s);
        out[g * 2 + j] = s;
    }
}

// ---------------- launch ----------------

static float* sym_addr(const void* sym) {
    void* p = nullptr;
    cudaGetSymbolAddress(&p, sym);
    return (float*)p;
}

extern "C" void kernel_launch(void* const* d_in, const int* in_sizes, int n_in,
                              void* d_out, int out_size) {
    const float* feat    = (const float*)d_in[0];
    const int*   src     = (const int*)d_in[1];
    const int*   dst     = (const int*)d_in[2];
    const int*   gid     = (const int*)d_in[3];
    const float* W_self1 = (const float*)d_in[4];
    const float* W_neigh1= (const float*)d_in[5];
    const float* b1      = (const float*)d_in[6];
    const float* W_self2 = (const float*)d_in[7];
    const float* W_neigh2= (const float*)d_in[8];
    const float* b2      = (const float*)d_in[9];
    const float* W_self3 = (const float*)d_in[10];
    const float* W_neigh3= (const float*)d_in[11];
    const float* b3      = (const float*)d_in[12];
    const float* W_cls   = (const float*)d_in[13];
    const float* b_cls   = (const float*)d_in[14];

    float* out      = (float*)d_out;         // [16, 2]
    float* out_feat = out + N_GRAPHS * 2;    // [16, 64]
    float* h3       = out_feat + N_GRAPHS * D_H; // [10000, 64]

    float* p_agg  = sym_addr(g_agg);
    float* p_h1   = sym_addr(g_h1);
    float* p_h2   = sym_addr(g_h2);
    float* p_deg  = sym_addr(g_deg);
    float* p_gsum = sym_addr(g_gsum);
    float* p_gcnt = sym_addr(g_gcnt);

    const int ZT = 256;
    dim3 projBlk(64, 4);
    int projGrid = (N_NODES + 3) / 4;
    unsigned scatTot = (unsigned)N_EDGES * 16u;
    int scatGrid = (int)((scatTot + 255u) / 256u);
    int finGrid = (N_NODES * D_H + 255) / 256;

    // degrees + graph counts
    zero_f<<<(N_NODES + ZT - 1) / ZT, ZT>>>(p_deg, N_NODES);
    zero_f<<<1, N_GRAPHS>>>(p_gcnt, N_GRAPHS);
    zero_f<<<(N_GRAPHS * D_H + ZT - 1) / ZT, ZT>>>(p_gsum, N_GRAPHS * D_H);
    deg_gcnt_kernel<<<(N_EDGES + N_NODES + ZT - 1) / ZT, ZT>>>(dst, gid);

    // ---- layer 1 (K=256), relu ----
    project_kernel<D_IN><<<projGrid, projBlk>>>(feat, W_self1, W_neigh1, b1);
    zero_f<<<finGrid, ZT>>>(p_agg, N_NODES * D_H);
    scatter_kernel<<<scatGrid, 256>>>(src, dst);
    finalize_kernel<true><<<finGrid, 256>>>(p_h1);

    // ---- layer 2 (K=64), relu ----
    project_kernel<D_H><<<projGrid, projBlk>>>(p_h1, W_self2, W_neigh2, b2);
    zero_f<<<finGrid, ZT>>>(p_agg, N_NODES * D_H);
    scatter_kernel<<<scatGrid, 256>>>(src, dst);
    finalize_kernel<true><<<finGrid, 256>>>(p_h2);

    // ---- layer 3 (K=64), no relu, writes h3 straight into d_out ----
    project_kernel<D_H><<<projGrid, projBlk>>>(p_h2, W_self3, W_neigh3, b3);
    zero_f<<<finGrid, ZT>>>(p_agg, N_NODES * D_H);
    scatter_kernel<<<scatGrid, 256>>>(src, dst);
    finalize_kernel<false><<<finGrid, 256>>>(h3);

    // ---- readout + head ----
    readout_kernel<<<(N_NODES + 249) / 250, 64>>>(h3, gid);
    head_kernel<<<1, 256>>>(W_cls, b_cls, out, out_feat);
}

// round 2
// speedup vs baseline: 1.0843x; 1.0843x over previous
#include <cuda_runtime.h>

#define N_NODES  10000
#define N_EDGES  320000
#define N_GRAPHS 16
#define D_IN     256
#define D_H      64

// ---------------- device scratch (no allocations allowed) ----------------
__device__ float g_S[N_NODES * D_H];       // self projection (+bias)
__device__ float g_X[N_NODES * D_H];       // neighbor projection
__device__ float g_h1[N_NODES * D_H];      // layer1 output
__device__ float g_h2[N_NODES * D_H];      // layer2 output
__device__ int   g_rowcnt[N_NODES];        // in-degree histogram
__device__ int   g_rowptr[N_NODES + 1];    // CSR row pointers (by dst)
__device__ int   g_cursor[N_NODES];        // placement cursors
__device__ int   g_csr[N_EDGES];           // CSR column indices (src)

// ---------------- small helpers ----------------

__device__ __forceinline__ unsigned long long pack2(float lo, float hi) {
    unsigned long long r;
    asm("mov.b64 %0, {%1, %2};" : "=l"(r) : "f"(lo), "f"(hi));
    return r;
}
__device__ __forceinline__ float2 unpack2(unsigned long long v) {
    float2 r;
    asm("mov.b64 {%0, %1}, %2;" : "=f"(r.x), "=f"(r.y) : "l"(v));
    return r;
}
__device__ __forceinline__ void ffma2(unsigned long long& d,
                                      unsigned long long a,
                                      unsigned long long b) {
    asm("fma.rn.f32x2 %0, %1, %2, %0;" : "+l"(d) : "l"(a), "l"(b));
}

__device__ __forceinline__ int warp_incl_scan(int v) {
    int lane = threadIdx.x & 31;
#pragma unroll
    for (int o = 1; o < 32; o <<= 1) {
        int n = __shfl_up_sync(0xffffffffu, v, o);
        if (lane >= o) v += n;
    }
    return v;
}

// ---------------- CSR build ----------------

// histogram of dst (4 edges per thread)
__global__ void hist_kernel(const int* __restrict__ dst) {
    int t = blockIdx.x * blockDim.x + threadIdx.x;
    if (t * 4 >= N_EDGES) return;
    int4 d4 = *reinterpret_cast<const int4*>(dst + t * 4);
    atomicAdd(&g_rowcnt[d4.x], 1);
    atomicAdd(&g_rowcnt[d4.y], 1);
    atomicAdd(&g_rowcnt[d4.z], 1);
    atomicAdd(&g_rowcnt[d4.w], 1);
}

// single-block prefix sum over 10000 counts -> rowptr, cursor
__global__ void scan_kernel() {
    __shared__ int wsum[32];
    __shared__ int s_total;
    int tid  = threadIdx.x;
    int lane = tid & 31;
    int wid  = tid >> 5;
    int running = 0;

    for (int chunk = 0; chunk < (N_NODES + 1023) / 1024; chunk++) {
        int i = chunk * 1024 + tid;
        int v = (i < N_NODES) ? g_rowcnt[i] : 0;
        int incl = warp_incl_scan(v);
        if (lane == 31) wsum[wid] = incl;
        __syncthreads();
        if (wid == 0) {
            int wv = wsum[lane];
            int wincl = warp_incl_scan(wv);
            wsum[lane] = wincl;
            if (lane == 31) s_total = wincl;
        }
        __syncthreads();
        int base = (wid > 0) ? wsum[wid - 1] : 0;
        incl += base;
        if (i < N_NODES) {
            g_rowptr[i + 1] = running + incl;
            g_cursor[i]     = running + incl - v;
        }
        if (tid == 0 && chunk == 0) g_rowptr[0] = 0;
        running += s_total;
        __syncthreads();
    }
}

// place src indices into CSR slots (4 edges per thread)
__global__ void place_kernel(const int* __restrict__ src,
                             const int* __restrict__ dst) {
    int t = blockIdx.x * blockDim.x + threadIdx.x;
    if (t * 4 >= N_EDGES) return;
    int4 s4 = *reinterpret_cast<const int4*>(src + t * 4);
    int4 d4 = *reinterpret_cast<const int4*>(dst + t * 4);
    g_csr[atomicAdd(&g_cursor[d4.x], 1)] = s4.x;
    g_csr[atomicAdd(&g_cursor[d4.y], 1)] = s4.y;
    g_csr[atomicAdd(&g_cursor[d4.z], 1)] = s4.z;
    g_csr[atomicAdd(&g_cursor[d4.w], 1)] = s4.w;
}

// ---------------- projection: S = A@Wself + b, X = A@Wneigh ----------------
// block (32,8): 8 rows, each thread does 2 adjacent output columns via f32x2 FMA
template <int K>
__global__ void project_kernel(const float* __restrict__ A,
                               const float* __restrict__ Wself,
                               const float* __restrict__ Wneigh,
                               const float* __restrict__ b) {
    __shared__ float sA[8][K];
    int cp  = threadIdx.x;               // column pair 0..31 -> cols 2cp,2cp+1
    int ty  = threadIdx.y;               // 0..7
    int row = blockIdx.x * 8 + ty;       // N_NODES % 8 == 0, no bounds needed

    for (int idx = ty * 32 + cp; idx < 8 * K; idx += 256)
        sA[idx / K][idx % K] = A[(blockIdx.x * 8 + idx / K) * K + idx % K];
    __syncthreads();

    const unsigned long long* Ws = reinterpret_cast<const unsigned long long*>(Wself);
    const unsigned long long* Wn = reinterpret_cast<const unsigned long long*>(Wneigh);

    unsigned long long s2 = 0ull, x2 = 0ull;
#pragma unroll 16
    for (int k = 0; k < K; k++) {
        float a = sA[ty][k];
        unsigned long long a2 = pack2(a, a);
        ffma2(s2, a2, Ws[k * 32 + cp]);
        ffma2(x2, a2, Wn[k * 32 + cp]);
    }
    float2 s = unpack2(s2);
    float2 x = unpack2(x2);
    s.x += b[2 * cp];
    s.y += b[2 * cp + 1];
    *reinterpret_cast<float2*>(g_S + row * D_H + 2 * cp) = s;
    *reinterpret_cast<float2*>(g_X + row * D_H + 2 * cp) = x;
}

// ---------------- gather + finalize: out = act(S + mean_{j in N(i)} X_j) ----
// 16 threads per node (one float4 each); 160000 threads = 625 blocks exactly
template <bool RELU>
__global__ void gather_kernel(float* __restrict__ out) {
    int t    = blockIdx.x * blockDim.x + threadIdx.x;
    int node = t >> 4;
    int lane = t & 15;

    int beg = g_rowptr[node];
    int end = g_rowptr[node + 1];

    float4 acc = make_float4(0.f, 0.f, 0.f, 0.f);
    int p = beg;
    for (; p + 1 < end; p += 2) {
        int s0 = g_csr[p];
        int s1 = g_csr[p + 1];
        float4 v0 = *reinterpret_cast<const float4*>(g_X + s0 * D_H + lane * 4);
        float4 v1 = *reinterpret_cast<const float4*>(g_X + s1 * D_H + lane * 4);
        acc.x += v0.x; acc.y += v0.y; acc.z += v0.z; acc.w += v0.w;
        acc.x += v1.x; acc.y += v1.y; acc.z += v1.z; acc.w += v1.w;
    }
    if (p < end) {
        int s0 = g_csr[p];
        float4 v0 = *reinterpret_cast<const float4*>(g_X + s0 * D_H + lane * 4);
        acc.x += v0.x; acc.y += v0.y; acc.z += v0.z; acc.w += v0.w;
    }

    float inv = 1.f / fmaxf((float)(end - beg), 1.f);
    float4 s4 = *reinterpret_cast<const float4*>(g_S + node * D_H + lane * 4);
    float4 o;
    o.x = s4.x + acc.x * inv;
    o.y = s4.y + acc.y * inv;
    o.z = s4.z + acc.z * inv;
    o.w = s4.w + acc.w * inv;
    if (RELU) {
        o.x = fmaxf(o.x, 0.f); o.y = fmaxf(o.y, 0.f);
        o.z = fmaxf(o.z, 0.f); o.w = fmaxf(o.w, 0.f);
    }
    *reinterpret_cast<float4*>(out + node * D_H + lane * 4) = o;
}

// ---------------- readout + head (graph_id is sorted -> contiguous segments)
__device__ __forceinline__ int lower_bound_gid(const int* gid, int key) {
    int lo = 0, hi = N_NODES;
    while (lo < hi) {
        int mid = (lo + hi) >> 1;
        if (gid[mid] < key) lo = mid + 1; else hi = mid;
    }
    return lo;
}

__global__ void readout_head_kernel(const float* __restrict__ h,
                                    const int* __restrict__ gid,
                                    const float* __restrict__ Wcls,
                                    const float* __restrict__ bcls,
                                    float* __restrict__ out,
                                    float* __restrict__ out_feat) {
    __shared__ int s_beg, s_end;
    __shared__ float red[4][D_H];
    int g = blockIdx.x;
    if (threadIdx.x == 0) {
        s_beg = lower_bound_gid(gid, g);
        s_end = lower_bound_gid(gid, g + 1);
    }
    __syncthreads();
    int beg = s_beg, end = s_end;
    int c = threadIdx.x & 63;
    int r = threadIdx.x >> 6;   // 0..3

    float acc = 0.f;
    for (int i = beg + r; i < end; i += 4)
        acc += h[i * D_H + c];
    red[r][c] = acc;
    __syncthreads();
    if (r == 0) {
        float m = (red[0][c] + red[1][c] + red[2][c] + red[3][c]) /
                  fmaxf((float)(end - beg), 1.f);
        out_feat[g * D_H + c] = m;
        red[0][c] = m;
    }
    __syncthreads();
    if (threadIdx.x < 2) {
        int j = threadIdx.x;
        float s = bcls[j];
#pragma unroll
        for (int k = 0; k < D_H; k++)
            s = fmaf(red[0][k], Wcls[k * 2 + j], s);
        out[g * 2 + j] = s;
    }
}

// ---------------- launch ----------------

template <typename T>
static T* sym_addr(const void* sym) {
    void* p = nullptr;
    cudaGetSymbolAddress(&p, sym);
    return (T*)p;
}

extern "C" void kernel_launch(void* const* d_in, const int* in_sizes, int n_in,
                              void* d_out, int out_size) {
    const float* feat     = (const float*)d_in[0];
    const int*   src      = (const int*)d_in[1];
    const int*   dst      = (const int*)d_in[2];
    const int*   gid      = (const int*)d_in[3];
    const float* W_self1  = (const float*)d_in[4];
    const float* W_neigh1 = (const float*)d_in[5];
    const float* b1       = (const float*)d_in[6];
    const float* W_self2  = (const float*)d_in[7];
    const float* W_neigh2 = (const float*)d_in[8];
    const float* b2       = (const float*)d_in[9];
    const float* W_self3  = (const float*)d_in[10];
    const float* W_neigh3 = (const float*)d_in[11];
    const float* b3       = (const float*)d_in[12];
    const float* W_cls    = (const float*)d_in[13];
    const float* b_cls    = (const float*)d_in[14];

    float* out      = (float*)d_out;                  // [16, 2]
    float* out_feat = out + N_GRAPHS * 2;             // [16, 64]
    float* h3       = out_feat + N_GRAPHS * D_H;      // [10000, 64]

    float* p_h1 = sym_addr<float>(g_h1);
    float* p_h2 = sym_addr<float>(g_h2);
    int* p_rowcnt = sym_addr<int>(g_rowcnt);

    dim3 projBlk(32, 8);
    const int projGrid = N_NODES / 8;                 // 1250
    const int edgeGrid = (N_EDGES / 4 + 255) / 256;   // 313
    const int gatherGrid = N_NODES * 16 / 256;        // 625

    // ---- CSR build ----
    cudaMemsetAsync(p_rowcnt, 0, N_NODES * sizeof(int));
    hist_kernel<<<edgeGrid, 256>>>(dst);
    scan_kernel<<<1, 1024>>>();
    place_kernel<<<edgeGrid, 256>>>(src, dst);

    // ---- layer 1 (K=256), relu ----
    project_kernel<D_IN><<<projGrid, projBlk>>>(feat, W_self1, W_neigh1, b1);
    gather_kernel<true><<<gatherGrid, 256>>>(p_h1);

    // ---- layer 2 (K=64), relu ----
    project_kernel<D_H><<<projGrid, projBlk>>>(p_h1, W_self2, W_neigh2, b2);
    gather_kernel<true><<<gatherGrid, 256>>>(p_h2);

    // ---- layer 3 (K=64), no relu -> h3 straight into d_out ----
    project_kernel<D_H><<<projGrid, projBlk>>>(p_h2, W_self3, W_neigh3, b3);
    gather_kernel<false><<<gatherGrid, 256>>>(h3);

    // ---- readout + head ----
    readout_head_kernel<<<N_GRAPHS, 256>>>(h3, gid, W_cls, b_cls, out, out_feat);
}

// round 3
// speedup vs baseline: 1.6793x; 1.5488x over previous
#include <cuda_runtime.h>

#define N_NODES  10000
#define N_EDGES  320000
#define N_GRAPHS 16
#define D_IN     256
#define D_H      64

// ---------------- device scratch (no allocations allowed) ----------------
__device__ float g_S[N_NODES * D_H];       // self projection (+bias)
__device__ float g_X[N_NODES * D_H];       // neighbor projection
__device__ float g_h1[N_NODES * D_H];      // layer1 output
__device__ float g_h2[N_NODES * D_H];      // layer2 output
__device__ int   g_rowcnt[N_NODES];        // in-degree histogram
__device__ int   g_rowptr[N_NODES + 1];    // CSR row pointers (by dst)
__device__ int   g_cursor[N_NODES];        // placement cursors
__device__ int   g_csr[N_EDGES];           // CSR column indices (src)

// ---------------- small helpers ----------------

__device__ __forceinline__ unsigned long long pack2(float lo, float hi) {
    unsigned long long r;
    asm("mov.b64 %0, {%1, %2};" : "=l"(r) : "f"(lo), "f"(hi));
    return r;
}
__device__ __forceinline__ float2 unpack2(unsigned long long v) {
    float2 r;
    asm("mov.b64 {%0, %1}, %2;" : "=f"(r.x), "=f"(r.y) : "l"(v));
    return r;
}
__device__ __forceinline__ void ffma2(unsigned long long& d,
                                      unsigned long long a,
                                      unsigned long long b) {
    asm("fma.rn.f32x2 %0, %1, %2, %0;" : "+l"(d) : "l"(a), "l"(b));
}

__device__ __forceinline__ int warp_incl_scan(int v) {
    int lane = threadIdx.x & 31;
#pragma unroll
    for (int o = 1; o < 32; o <<= 1) {
        int n = __shfl_up_sync(0xffffffffu, v, o);
        if (lane >= o) v += n;
    }
    return v;
}

// ---------------- CSR build ----------------

__global__ void hist_kernel(const int* __restrict__ dst) {
    int t = blockIdx.x * blockDim.x + threadIdx.x;
    if (t * 4 >= N_EDGES) return;
    int4 d4 = *reinterpret_cast<const int4*>(dst + t * 4);
    atomicAdd(&g_rowcnt[d4.x], 1);
    atomicAdd(&g_rowcnt[d4.y], 1);
    atomicAdd(&g_rowcnt[d4.z], 1);
    atomicAdd(&g_rowcnt[d4.w], 1);
}

// single-block prefix sum over 10000 counts -> rowptr, cursor
__global__ void scan_kernel() {
    __shared__ int wsum[32];
    __shared__ int s_total;
    int tid  = threadIdx.x;
    int lane = tid & 31;
    int wid  = tid >> 5;
    int running = 0;

    for (int chunk = 0; chunk < (N_NODES + 1023) / 1024; chunk++) {
        int i = chunk * 1024 + tid;
        int v = (i < N_NODES) ? g_rowcnt[i] : 0;
        int incl = warp_incl_scan(v);
        if (lane == 31) wsum[wid] = incl;
        __syncthreads();
        if (wid == 0) {
            int wv = wsum[lane];
            int wincl = warp_incl_scan(wv);
            wsum[lane] = wincl;
            if (lane == 31) s_total = wincl;
        }
        __syncthreads();
        int base = (wid > 0) ? wsum[wid - 1] : 0;
        incl += base;
        if (i < N_NODES) {
            g_rowptr[i + 1] = running + incl;
            g_cursor[i]     = running + incl - v;
        }
        if (tid == 0 && chunk == 0) g_rowptr[0] = 0;
        running += s_total;
        __syncthreads();
    }
}

__global__ void place_kernel(const int* __restrict__ src,
                             const int* __restrict__ dst) {
    int t = blockIdx.x * blockDim.x + threadIdx.x;
    if (t * 4 >= N_EDGES) return;
    int4 s4 = *reinterpret_cast<const int4*>(src + t * 4);
    int4 d4 = *reinterpret_cast<const int4*>(dst + t * 4);
    g_csr[atomicAdd(&g_cursor[d4.x], 1)] = s4.x;
    g_csr[atomicAdd(&g_cursor[d4.y], 1)] = s4.y;
    g_csr[atomicAdd(&g_cursor[d4.z], 1)] = s4.z;
    g_csr[atomicAdd(&g_cursor[d4.w], 1)] = s4.w;
}

// ---------------- projection: S = A@Wself + b, X = A@Wneigh ----------------
// Register-blocked GEMM. Block = 256 threads (32 col-pairs x 8), computes a
// 64-row x 128-col tile. Each thread: 8 rows x 1 col-pair x 2 matrices of
// f32x2 accumulators. W loads (2x LDG.64 per k) amortized over 8 rows.
template <int K>
__global__ void __launch_bounds__(256, 2)
project_kernel(const float* __restrict__ A,
               const float* __restrict__ Wself,
               const float* __restrict__ Wneigh,
               const float* __restrict__ b) {
    __shared__ float4 sA[64][8];            // 64 rows x 32 k (as 8 float4)
    const int cp   = threadIdx.x;           // col pair 0..31 -> cols 2cp,2cp+1
    const int ty   = threadIdx.y;           // 0..7
    const int tid  = ty * 32 + cp;
    const int base = blockIdx.x * 64;

    const unsigned long long* Ws = reinterpret_cast<const unsigned long long*>(Wself);
    const unsigned long long* Wn = reinterpret_cast<const unsigned long long*>(Wneigh);

    unsigned long long s2[8], x2[8];
#pragma unroll
    for (int r = 0; r < 8; r++) { s2[r] = 0ull; x2[r] = 0ull; }

    for (int kt = 0; kt < K / 32; kt++) {
        // load A tile: rows [base, base+64), k [kt*32, kt*32+32)
        __syncthreads();
#pragma unroll
        for (int i = 0; i < 2; i++) {
            int idx  = tid + i * 256;        // 0..511
            int row  = idx >> 3;
            int fcol = idx & 7;
            int grow = base + row;
            float4 v = make_float4(0.f, 0.f, 0.f, 0.f);
            if (grow < N_NODES)
                v = *reinterpret_cast<const float4*>(A + grow * K + kt * 32 + fcol * 4);
            sA[row][fcol] = v;
        }
        __syncthreads();

#pragma unroll
        for (int k4 = 0; k4 < 8; k4++) {
            float4 a[8];
#pragma unroll
            for (int r = 0; r < 8; r++)
                a[r] = sA[ty * 8 + r][k4];   // uniform per warp -> LDS broadcast
#pragma unroll
            for (int kk = 0; kk < 4; kk++) {
                int k = kt * 32 + k4 * 4 + kk;
                unsigned long long ws = Ws[k * 32 + cp];
                unsigned long long wn = Wn[k * 32 + cp];
#pragma unroll
                for (int r = 0; r < 8; r++) {
                    float av = (kk == 0) ? a[r].x : (kk == 1) ? a[r].y
                             : (kk == 2) ? a[r].z : a[r].w;
                    unsigned long long a2 = pack2(av, av);
                    ffma2(s2[r], a2, ws);
                    ffma2(x2[r], a2, wn);
                }
            }
        }
    }

    float bx = b[2 * cp], by = b[2 * cp + 1];
#pragma unroll
    for (int r = 0; r < 8; r++) {
        int row = base + ty * 8 + r;
        if (row >= N_NODES) break;
        float2 s = unpack2(s2[r]);
        float2 x = unpack2(x2[r]);
        s.x += bx; s.y += by;
        *reinterpret_cast<float2*>(g_S + row * D_H + 2 * cp) = s;
        *reinterpret_cast<float2*>(g_X + row * D_H + 2 * cp) = x;
    }
}

// ---------------- gather + finalize: out = act(S + mean_{j in N(i)} X_j) ----
template <bool RELU>
__global__ void gather_kernel(float* __restrict__ out) {
    int t    = blockIdx.x * blockDim.x + threadIdx.x;
    int node = t >> 4;
    int lane = t & 15;

    int beg = g_rowptr[node];
    int end = g_rowptr[node + 1];

    float4 acc = make_float4(0.f, 0.f, 0.f, 0.f);
    int p = beg;
    for (; p + 1 < end; p += 2) {
        int s0 = g_csr[p];
        int s1 = g_csr[p + 1];
        float4 v0 = *reinterpret_cast<const float4*>(g_X + s0 * D_H + lane * 4);
        float4 v1 = *reinterpret_cast<const float4*>(g_X + s1 * D_H + lane * 4);
        acc.x += v0.x; acc.y += v0.y; acc.z += v0.z; acc.w += v0.w;
        acc.x += v1.x; acc.y += v1.y; acc.z += v1.z; acc.w += v1.w;
    }
    if (p < end) {
        int s0 = g_csr[p];
        float4 v0 = *reinterpret_cast<const float4*>(g_X + s0 * D_H + lane * 4);
        acc.x += v0.x; acc.y += v0.y; acc.z += v0.z; acc.w += v0.w;
    }

    float inv = 1.f / fmaxf((float)(end - beg), 1.f);
    float4 s4 = *reinterpret_cast<const float4*>(g_S + node * D_H + lane * 4);
    float4 o;
    o.x = s4.x + acc.x * inv;
    o.y = s4.y + acc.y * inv;
    o.z = s4.z + acc.z * inv;
    o.w = s4.w + acc.w * inv;
    if (RELU) {
        o.x = fmaxf(o.x, 0.f); o.y = fmaxf(o.y, 0.f);
        o.z = fmaxf(o.z, 0.f); o.w = fmaxf(o.w, 0.f);
    }
    *reinterpret_cast<float4*>(out + node * D_H + lane * 4) = o;
}

// ---------------- readout + head (graph_id sorted -> contiguous segments) ---
__device__ __forceinline__ int lower_bound_gid(const int* gid, int key) {
    int lo = 0, hi = N_NODES;
    while (lo < hi) {
        int mid = (lo + hi) >> 1;
        if (gid[mid] < key) lo = mid + 1; else hi = mid;
    }
    return lo;
}

__global__ void readout_head_kernel(const float* __restrict__ h,
                                    const int* __restrict__ gid,
                                    const float* __restrict__ Wcls,
                                    const float* __restrict__ bcls,
                                    float* __restrict__ out,
                                    float* __restrict__ out_feat) {
    __shared__ int s_beg, s_end;
    __shared__ float red[4][D_H];
    int g = blockIdx.x;
    if (threadIdx.x == 0) {
        s_beg = lower_bound_gid(gid, g);
        s_end = lower_bound_gid(gid, g + 1);
    }
    __syncthreads();
    int beg = s_beg, end = s_end;
    int c = threadIdx.x & 63;
    int r = threadIdx.x >> 6;   // 0..3

    float acc = 0.f;
    for (int i = beg + r; i < end; i += 4)
        acc += h[i * D_H + c];
    red[r][c] = acc;
    __syncthreads();
    if (r == 0) {
        float m = (red[0][c] + red[1][c] + red[2][c] + red[3][c]) /
                  fmaxf((float)(end - beg), 1.f);
        out_feat[g * D_H + c] = m;
        red[0][c] = m;
    }
    __syncthreads();
    if (threadIdx.x < 2) {
        int j = threadIdx.x;
        float s = bcls[j];
#pragma unroll
        for (int k = 0; k < D_H; k++)
            s = fmaf(red[0][k], Wcls[k * 2 + j], s);
        out[g * 2 + j] = s;
    }
}

// ---------------- launch ----------------

template <typename T>
static T* sym_addr(const void* sym) {
    void* p = nullptr;
    cudaGetSymbolAddress(&p, sym);
    return (T*)p;
}

extern "C" void kernel_launch(void* const* d_in, const int* in_sizes, int n_in,
                              void* d_out, int out_size) {
    const float* feat     = (const float*)d_in[0];
    const int*   src      = (const int*)d_in[1];
    const int*   dst      = (const int*)d_in[2];
    const int*   gid      = (const int*)d_in[3];
    const float* W_self1  = (const float*)d_in[4];
    const float* W_neigh1 = (const float*)d_in[5];
    const float* b1       = (const float*)d_in[6];
    const float* W_self2  = (const float*)d_in[7];
    const float* W_neigh2 = (const float*)d_in[8];
    const float* b2       = (const float*)d_in[9];
    const float* W_self3  = (const float*)d_in[10];
    const float* W_neigh3 = (const float*)d_in[11];
    const float* b3       = (const float*)d_in[12];
    const float* W_cls    = (const float*)d_in[13];
    const float* b_cls    = (const float*)d_in[14];

    float* out      = (float*)d_out;                  // [16, 2]
    float* out_feat = out + N_GRAPHS * 2;             // [16, 64]
    float* h3       = out_feat + N_GRAPHS * D_H;      // [10000, 64]

    float* p_h1 = sym_addr<float>(g_h1);
    float* p_h2 = sym_addr<float>(g_h2);
    int* p_rowcnt = sym_addr<int>(g_rowcnt);

    dim3 projBlk(32, 8);
    const int projGrid = (N_NODES + 63) / 64;         // 157
    const int edgeGrid = (N_EDGES / 4 + 255) / 256;   // 313
    const int gatherGrid = N_NODES * 16 / 256;        // 625

    // ---- CSR build ----
    cudaMemsetAsync(p_rowcnt, 0, N_NODES * sizeof(int));
    hist_kernel<<<edgeGrid, 256>>>(dst);
    scan_kernel<<<1, 1024>>>();
    place_kernel<<<edgeGrid, 256>>>(src, dst);

    // ---- layer 1 (K=256), relu ----
    project_kernel<D_IN><<<projGrid, projBlk>>>(feat, W_self1, W_neigh1, b1);
    gather_kernel<true><<<gatherGrid, 256>>>(p_h1);

    // ---- layer 2 (K=64), relu ----
    project_kernel<D_H><<<projGrid, projBlk>>>(p_h1, W_self2, W_neigh2, b2);
    gather_kernel<true><<<gatherGrid, 256>>>(p_h2);

    // ---- layer 3 (K=64), no relu -> h3 straight into d_out ----
    project_kernel<D_H><<<projGrid, projBlk>>>(p_h2, W_self3, W_neigh3, b3);
    gather_kernel<false><<<gatherGrid, 256>>>(h3);

    // ---- readout + head ----
    readout_head_kernel<<<N_GRAPHS, 256>>>(h3, gid, W_cls, b_cls, out, out_feat);
}

// round 4
// speedup vs baseline: 1.7843x; 1.0625x over previous
#include <cuda_runtime.h>
#include <cstdint>

#define N_NODES  10000
#define N_EDGES  320000
#define N_GRAPHS 16
#define D_IN     256
#define D_H      64

// ---------------- device scratch (no allocations allowed) ----------------
__device__ float g_S[N_NODES * D_H];       // self projection (+bias)
__device__ float g_X[N_NODES * D_H];       // neighbor projection
__device__ float g_h1[N_NODES * D_H];      // layer1 output
__device__ float g_h2[N_NODES * D_H];      // layer2 output
__device__ int   g_rowcnt[N_NODES];        // in-degree histogram
__device__ int   g_rowptr[N_NODES + 1];    // CSR row pointers (by dst)
__device__ int   g_cursor[N_NODES];        // placement cursors
__device__ int   g_csr[N_EDGES];           // CSR column indices (src)

// ---------------- small helpers ----------------

__device__ __forceinline__ unsigned long long pack2(float lo, float hi) {
    unsigned long long r;
    asm("mov.b64 %0, {%1, %2};" : "=l"(r) : "f"(lo), "f"(hi));
    return r;
}
__device__ __forceinline__ float2 unpack2(unsigned long long v) {
    float2 r;
    asm("mov.b64 {%0, %1}, %2;" : "=f"(r.x), "=f"(r.y) : "l"(v));
    return r;
}
__device__ __forceinline__ void ffma2(unsigned long long& d,
                                      unsigned long long a,
                                      unsigned long long b) {
    asm("fma.rn.f32x2 %0, %1, %2, %0;" : "+l"(d) : "l"(a), "l"(b));
}
__device__ __forceinline__ void cp_async16(uint32_t saddr, const void* gaddr) {
    asm volatile("cp.async.ca.shared.global [%0], [%1], 16;"
                 :: "r"(saddr), "l"(gaddr));
}
__device__ __forceinline__ void cp_commit() {
    asm volatile("cp.async.commit_group;");
}
template <int N>
__device__ __forceinline__ void cp_wait() {
    asm volatile("cp.async.wait_group %0;" :: "n"(N));
}

__device__ __forceinline__ int warp_incl_scan(int v) {
    int lane = threadIdx.x & 31;
#pragma unroll
    for (int o = 1; o < 32; o <<= 1) {
        int n = __shfl_up_sync(0xffffffffu, v, o);
        if (lane >= o) v += n;
    }
    return v;
}

// ---------------- CSR build ----------------

__global__ void hist_kernel(const int* __restrict__ dst) {
    int t = blockIdx.x * blockDim.x + threadIdx.x;
    if (t * 4 >= N_EDGES) return;
    int4 d4 = *reinterpret_cast<const int4*>(dst + t * 4);
    atomicAdd(&g_rowcnt[d4.x], 1);
    atomicAdd(&g_rowcnt[d4.y], 1);
    atomicAdd(&g_rowcnt[d4.z], 1);
    atomicAdd(&g_rowcnt[d4.w], 1);
}

// single-block prefix sum over 10000 counts -> rowptr, cursor
__global__ void scan_kernel() {
    __shared__ int wsum[32];
    __shared__ int s_total;
    int tid  = threadIdx.x;
    int lane = tid & 31;
    int wid  = tid >> 5;
    int running = 0;

    for (int chunk = 0; chunk < (N_NODES + 1023) / 1024; chunk++) {
        int i = chunk * 1024 + tid;
        int v = (i < N_NODES) ? g_rowcnt[i] : 0;
        int incl = warp_incl_scan(v);
        if (lane == 31) wsum[wid] = incl;
        __syncthreads();
        if (wid == 0) {
            int wv = wsum[lane];
            int wincl = warp_incl_scan(wv);
            wsum[lane] = wincl;
            if (lane == 31) s_total = wincl;
        }
        __syncthreads();
        int base = (wid > 0) ? wsum[wid - 1] : 0;
        incl += base;
        if (i < N_NODES) {
            g_rowptr[i + 1] = running + incl;
            g_cursor[i]     = running + incl - v;
        }
        if (tid == 0 && chunk == 0) g_rowptr[0] = 0;
        running += s_total;
        __syncthreads();
    }
}

__global__ void place_kernel(const int* __restrict__ src,
                             const int* __restrict__ dst) {
    int t = blockIdx.x * blockDim.x + threadIdx.x;
    if (t * 4 >= N_EDGES) return;
    int4 s4 = *reinterpret_cast<const int4*>(src + t * 4);
    int4 d4 = *reinterpret_cast<const int4*>(dst + t * 4);
    g_csr[atomicAdd(&g_cursor[d4.x], 1)] = s4.x;
    g_csr[atomicAdd(&g_cursor[d4.y], 1)] = s4.y;
    g_csr[atomicAdd(&g_cursor[d4.z], 1)] = s4.z;
    g_csr[atomicAdd(&g_cursor[d4.w], 1)] = s4.w;
}

// ---------------- projection: S = A@Wself + b, X = A@Wneigh ----------------
// Register-blocked GEMM, latency-tuned. Block = 256 threads (32 colpairs x 8),
// tile = 32 rows x 128 cols, 4 rows/thread, cp.async double-buffered A tile.
// grid = 313 (~2 waves), target 4 blocks/SM resident.
template <int K>
__global__ void __launch_bounds__(256, 4)
project_kernel(const float* __restrict__ A,
               const float* __restrict__ Wself,
               const float* __restrict__ Wneigh,
               const float* __restrict__ b) {
    constexpr int KT = K / 32;
    __shared__ float4 sA[2][32][8];          // 32 rows x 32 k, double buffered
    const int cp   = threadIdx.x;            // col pair 0..31
    const int ty   = threadIdx.y;            // 0..7
    const int tid  = ty * 32 + cp;           // 0..255
    const int base = blockIdx.x * 32;

    // this thread's A-tile staging slot: one float4
    const int ldrow = tid >> 3;               // 0..31
    const int ldk4  = tid & 7;                // 0..7
    int grow = base + ldrow;
    if (grow >= N_NODES) grow = N_NODES - 1;  // clamp: garbage rows never stored
    const float* gsrc = A + grow * K + ldk4 * 4;

    const unsigned long long* Ws = reinterpret_cast<const unsigned long long*>(Wself);
    const unsigned long long* Wn = reinterpret_cast<const unsigned long long*>(Wneigh);

    unsigned long long s2[4], x2[4];
#pragma unroll
    for (int r = 0; r < 4; r++) { s2[r] = 0ull; x2[r] = 0ull; }

    // prologue: stage kt=0
    cp_async16((uint32_t)__cvta_generic_to_shared(&sA[0][ldrow][ldk4]), gsrc);
    cp_commit();

#pragma unroll
    for (int kt = 0; kt < KT; kt++) {
        if (kt + 1 < KT) {
            cp_async16((uint32_t)__cvta_generic_to_shared(&sA[(kt + 1) & 1][ldrow][ldk4]),
                       gsrc + (kt + 1) * 32);
            cp_commit();
            cp_wait<1>();
        } else {
            cp_wait<0>();
        }
        __syncthreads();

        const int bufi = kt & 1;
#pragma unroll
        for (int k4 = 0; k4 < 8; k4++) {
            float4 a0 = sA[bufi][ty * 4 + 0][k4];
            float4 a1 = sA[bufi][ty * 4 + 1][k4];
            float4 a2 = sA[bufi][ty * 4 + 2][k4];
            float4 a3 = sA[bufi][ty * 4 + 3][k4];
#pragma unroll
            for (int kk = 0; kk < 4; kk++) {
                int k = kt * 32 + k4 * 4 + kk;
                unsigned long long ws = Ws[k * 32 + cp];
                unsigned long long wn = Wn[k * 32 + cp];
                float v0 = (kk == 0) ? a0.x : (kk == 1) ? a0.y : (kk == 2) ? a0.z : a0.w;
                float v1 = (kk == 0) ? a1.x : (kk == 1) ? a1.y : (kk == 2) ? a1.z : a1.w;
                float v2 = (kk == 0) ? a2.x : (kk == 1) ? a2.y : (kk == 2) ? a2.z : a2.w;
                float v3 = (kk == 0) ? a3.x : (kk == 1) ? a3.y : (kk == 2) ? a3.z : a3.w;
                unsigned long long p0 = pack2(v0, v0);
                unsigned long long p1 = pack2(v1, v1);
                unsigned long long p2 = pack2(v2, v2);
                unsigned long long p3 = pack2(v3, v3);
                ffma2(s2[0], p0, ws); ffma2(x2[0], p0, wn);
                ffma2(s2[1], p1, ws); ffma2(x2[1], p1, wn);
                ffma2(s2[2], p2, ws); ffma2(x2[2], p2, wn);
                ffma2(s2[3], p3, ws); ffma2(x2[3], p3, wn);
            }
        }
        __syncthreads();
    }

    float bx = b[2 * cp], by = b[2 * cp + 1];
#pragma unroll
    for (int r = 0; r < 4; r++) {
        int row = base + ty * 4 + r;
        if (row >= N_NODES) break;
        float2 s = unpack2(s2[r]);
        float2 x = unpack2(x2[r]);
        s.x += bx; s.y += by;
        *reinterpret_cast<float2*>(g_S + row * D_H + 2 * cp) = s;
        *reinterpret_cast<float2*>(g_X + row * D_H + 2 * cp) = x;
    }
}

// ---------------- gather + finalize: out = act(S + mean_{j in N(i)} X_j) ----
template <bool RELU>
__global__ void gather_kernel(float* __restrict__ out) {
    int t    = blockIdx.x * blockDim.x + threadIdx.x;
    int node = t >> 4;
    int lane = t & 15;

    int beg = g_rowptr[node];
    int end = g_rowptr[node + 1];

    float4 acc = make_float4(0.f, 0.f, 0.f, 0.f);
    int p = beg;
    for (; p + 1 < end; p += 2) {
        int s0 = g_csr[p];
        int s1 = g_csr[p + 1];
        float4 v0 = *reinterpret_cast<const float4*>(g_X + s0 * D_H + lane * 4);
        float4 v1 = *reinterpret_cast<const float4*>(g_X + s1 * D_H + lane * 4);
        acc.x += v0.x; acc.y += v0.y; acc.z += v0.z; acc.w += v0.w;
        acc.x += v1.x; acc.y += v1.y; acc.z += v1.z; acc.w += v1.w;
    }
    if (p < end) {
        int s0 = g_csr[p];
        float4 v0 = *reinterpret_cast<const float4*>(g_X + s0 * D_H + lane * 4);
        acc.x += v0.x; acc.y += v0.y; acc.z += v0.z; acc.w += v0.w;
    }

    float inv = 1.f / fmaxf((float)(end - beg), 1.f);
    float4 s4 = *reinterpret_cast<const float4*>(g_S + node * D_H + lane * 4);
    float4 o;
    o.x = s4.x + acc.x * inv;
    o.y = s4.y + acc.y * inv;
    o.z = s4.z + acc.z * inv;
    o.w = s4.w + acc.w * inv;
    if (RELU) {
        o.x = fmaxf(o.x, 0.f); o.y = fmaxf(o.y, 0.f);
        o.z = fmaxf(o.z, 0.f); o.w = fmaxf(o.w, 0.f);
    }
    *reinterpret_cast<float4*>(out + node * D_H + lane * 4) = o;
}

// ---------------- readout + head (graph_id sorted -> contiguous segments) ---
__device__ __forceinline__ int lower_bound_gid(const int* gid, int key) {
    int lo = 0, hi = N_NODES;
    while (lo < hi) {
        int mid = (lo + hi) >> 1;
        if (gid[mid] < key) lo = mid + 1; else hi = mid;
    }
    return lo;
}

__global__ void readout_head_kernel(const float* __restrict__ h,
                                    const int* __restrict__ gid,
                                    const float* __restrict__ Wcls,
                                    const float* __restrict__ bcls,
                                    float* __restrict__ out,
                                    float* __restrict__ out_feat) {
    __shared__ int s_beg, s_end;
    __shared__ float red[4][D_H];
    int g = blockIdx.x;
    if (threadIdx.x == 0) {
        s_beg = lower_bound_gid(gid, g);
        s_end = lower_bound_gid(gid, g + 1);
    }
    __syncthreads();
    int beg = s_beg, end = s_end;
    int c = threadIdx.x & 63;
    int r = threadIdx.x >> 6;   // 0..3

    float acc = 0.f;
    for (int i = beg + r; i < end; i += 4)
        acc += h[i * D_H + c];
    red[r][c] = acc;
    __syncthreads();
    if (r == 0) {
        float m = (red[0][c] + red[1][c] + red[2][c] + red[3][c]) /
                  fmaxf((float)(end - beg), 1.f);
        out_feat[g * D_H + c] = m;
        red[0][c] = m;
    }
    __syncthreads();
    if (threadIdx.x < 2) {
        int j = threadIdx.x;
        float s = bcls[j];
#pragma unroll
        for (int k = 0; k < D_H; k++)
            s = fmaf(red[0][k], Wcls[k * 2 + j], s);
        out[g * 2 + j] = s;
    }
}

// ---------------- launch ----------------

template <typename T>
static T* sym_addr(const void* sym) {
    void* p = nullptr;
    cudaGetSymbolAddress(&p, sym);
    return (T*)p;
}

extern "C" void kernel_launch(void* const* d_in, const int* in_sizes, int n_in,
                              void* d_out, int out_size) {
    const float* feat     = (const float*)d_in[0];
    const int*   src      = (const int*)d_in[1];
    const int*   dst      = (const int*)d_in[2];
    const int*   gid      = (const int*)d_in[3];
    const float* W_self1  = (const float*)d_in[4];
    const float* W_neigh1 = (const float*)d_in[5];
    const float* b1       = (const float*)d_in[6];
    const float* W_self2  = (const float*)d_in[7];
    const float* W_neigh2 = (const float*)d_in[8];
    const float* b2       = (const float*)d_in[9];
    const float* W_self3  = (const float*)d_in[10];
    const float* W_neigh3 = (const float*)d_in[11];
    const float* b3       = (const float*)d_in[12];
    const float* W_cls    = (const float*)d_in[13];
    const float* b_cls    = (const float*)d_in[14];

    float* out      = (float*)d_out;                  // [16, 2]
    float* out_feat = out + N_GRAPHS * 2;             // [16, 64]
    float* h3       = out_feat + N_GRAPHS * D_H;      // [10000, 64]

    float* p_h1 = sym_addr<float>(g_h1);
    float* p_h2 = sym_addr<float>(g_h2);
    int* p_rowcnt = sym_addr<int>(g_rowcnt);

    dim3 projBlk(32, 8);
    const int projGrid = (N_NODES + 31) / 32;         // 313
    const int edgeGrid = (N_EDGES / 4 + 255) / 256;   // 313
    const int gatherGrid = N_NODES * 16 / 256;        // 625

    // ---- CSR build ----
    cudaMemsetAsync(p_rowcnt, 0, N_NODES * sizeof(int));
    hist_kernel<<<edgeGrid, 256>>>(dst);
    scan_kernel<<<1, 1024>>>();
    place_kernel<<<edgeGrid, 256>>>(src, dst);

    // ---- layer 1 (K=256), relu ----
    project_kernel<D_IN><<<projGrid, projBlk>>>(feat, W_self1, W_neigh1, b1);
    gather_kernel<true><<<gatherGrid, 256>>>(p_h1);

    // ---- layer 2 (K=64), relu ----
    project_kernel<D_H><<<projGrid, projBlk>>>(p_h1, W_self2, W_neigh2, b2);
    gather_kernel<true><<<gatherGrid, 256>>>(p_h2);

    // ---- layer 3 (K=64), no relu -> h3 straight into d_out ----
    project_kernel<D_H><<<projGrid, projBlk>>>(p_h2, W_self3, W_neigh3, b3);
    gather_kernel<false><<<gatherGrid, 256>>>(h3);

    // ---- readout + head ----
    readout_head_kernel<<<N_GRAPHS, 256>>>(h3, gid, W_cls, b_cls, out, out_feat);
}